// round 8
// baseline (speedup 1.0000x reference)
#include <cuda_runtime.h>
#include <cstdint>

#define B_SZ 256
#define T_SZ 168
#define LAG 168
#define LAT 128
#define WS 64
#define H_SZ 1024

#define KC 64
#define PITCH 68                 // 68 % 32 == 4 -> conflict-free frag reads
#define A_ROWS 64
#define B_ROWS 96
#define STAGE_FLOATS ((A_ROWS + B_ROWS) * PITCH)   // 10880 floats / stage
#define RED_PITCH 52
#define GRID_CTAS 128
#define NTHREADS 256

// ---- device scratch (no allocations allowed) ----
__device__ float g_hbuf[2][B_SZ * H_SZ];   // ping-pong GRU state
__device__ float g_e2[B_SZ * LAT];
__device__ unsigned g_cnt;                 // grid barrier arrivals (monotonic, replay-safe)
__device__ unsigned g_gen;                 // grid barrier generation (monotonic)

__device__ __forceinline__ float leakyf(float x) { return x >= 0.f ? x : 0.01f * x; }
__device__ __forceinline__ float sigmoidf_(float x) { return 1.f / (1.f + expf(-x)); }
__device__ __forceinline__ float rna_tf32(float x) {
    uint32_t o;
    asm("cvt.rna.tf32.f32 %0, %1;" : "=r"(o) : "f"(x));
    return __uint_as_float(o);
}
__device__ __forceinline__ void cp16(void* sdst, const void* gsrc) {
    uint32_t s = (uint32_t)__cvta_generic_to_shared(sdst);
    asm volatile("cp.async.cg.shared.global [%0], [%1], 16;" ::"r"(s), "l"(gsrc));
}
__device__ __forceinline__ void cp_commit() { asm volatile("cp.async.commit_group;"); }
template <int N>
__device__ __forceinline__ void cp_wait() { asm volatile("cp.async.wait_group %0;" ::"n"(N)); }

#define BAR_ALL() asm volatile("bar.sync 0, 256;" ::: "memory")
#define BAR_G0()  asm volatile("bar.sync 1, 128;" ::: "memory")
#define BAR_G1()  asm volatile("bar.sync 2, 128;" ::: "memory")

// Grid barrier: wait until all 128 CTAs reach generation `target` (absolute,
// computed from the g_gen snapshot taken at kernel entry -> replay-safe).
__device__ __forceinline__ void grid_bar(unsigned target, int tid) {
    __threadfence();
    BAR_ALL();
    if (tid == 0) {
        unsigned prev = atomicAdd(&g_cnt, 1u);
        if (prev + 1u == target * (unsigned)GRID_CTAS) {
            __threadfence();
            *(volatile unsigned*)&g_gen = target;
        } else {
            while ((int)(*(volatile unsigned*)&g_gen - target) < 0) {}
        }
        __threadfence();
    }
    BAR_ALL();
}

// ================= the whole model, one persistent kernel =================
// grid = 128 CTAs = 4 m-tiles (64 batch rows) x 32 n-tiles (32 hidden units).
// 8 warps: warps 0-3 = K-group 0 (input GEMM + hidden K[0,512), stages 0-2),
//          warps 4-7 = K-group 1 (hidden K[512,1024), stages 3-4).
// Each group: 2m x 2n warps, warp tile 32 rows x 48 gate cols, tf32 m16n8k8.
__global__ void __launch_bounds__(NTHREADS, 1) crnn_all(
    const float* __restrict__ lag, const float* __restrict__ curr,
    const float* __restrict__ W1, const float* __restrict__ b1,
    const float* __restrict__ W2, const float* __restrict__ b2,
    const float* __restrict__ W3, const float* __restrict__ b3,
    const float* __restrict__ Wih, const float* __restrict__ Whh,
    const float* __restrict__ bih, const float* __restrict__ bhh,
    const float* __restrict__ Wo, const float* __restrict__ bo,
    float* __restrict__ out) {
    extern __shared__ float smem[];
    float* red = smem + 3 * STAGE_FLOATS;  // reuses stage-3 region at exchange time

    const int tid = threadIdx.x;
    const int blk = blockIdx.x;
    const unsigned base = *(volatile unsigned*)&g_gen;  // entry snapshot (stable: no CTA
                                                        // bumps g_gen before all read it)

    // ---------------- phase E: out init + enc1 + enc2 (2 batch rows / CTA) ----------------
    {
        float bov = bo[0];
        for (int i = tid; i < 336; i += NTHREADS) out[blk * 336 + i] = bov;
        int hid = tid >> 7, ht = tid & 127;
        int row = blk * 2 + hid;
        float* lagbuf = smem + hid * LAG;
        float* e1buf = smem + 2 * LAG + hid * 64;
        for (int i = ht; i < LAG; i += 128) lagbuf[i] = lag[row * LAG + i];
        __syncthreads();
        if (ht < 64) {
            float acc = b1[ht];
            const float* w = W1 + ht * LAG;
#pragma unroll 4
            for (int k = 0; k < LAG; ++k) acc += lagbuf[k] * w[k];
            e1buf[ht] = leakyf(acc);
        }
        __syncthreads();
        {
            float acc = b2[ht];
            const float* w = W2 + ht * 64;
#pragma unroll 8
            for (int k = 0; k < 64; ++k) acc += e1buf[k] * w[k];
            g_e2[row * LAT + ht] = leakyf(acc);
        }
    }
    grid_bar(base + 1, tid);

    // ---------------- phase E3: h0 = leaky-free (e2 @ W3.T + b3), 2 rows / CTA ----------------
    {
        float* e2buf = smem;
        e2buf[tid] = g_e2[blk * 256 + tid];
        __syncthreads();
#pragma unroll
        for (int rr = 0; rr < 2; ++rr)
#pragma unroll
            for (int q = 0; q < 4; ++q) {
                int col = tid + q * 256;
                float acc = b3[col];
                const float* w = W3 + (size_t)col * LAT;
                const float* e = e2buf + rr * LAT;
#pragma unroll 8
                for (int k = 0; k < LAT; ++k) acc += e[k] * w[k];
                g_hbuf[0][(size_t)(blk * 2 + rr) * H_SZ + col] = rna_tf32(acc);
            }
    }
    grid_bar(base + 2, tid);

    // ---------------- persistent GRU ----------------
    const int warp = tid >> 5, lane = tid & 31;
    const int gid = lane >> 2, tig = lane & 3;
    const int grp = warp >> 2;
    const int wi = warp & 3;
    const int wm = wi & 1, wn = wi >> 1;
    const int wrow = wm * 32;
    const int cb = wn * 48;
    const int tidg = tid & 127;
    const int nt = blk & 31, mt = blk >> 5;
    const int m0 = mt * 64;
    const int jb0 = nt * 32;
    const int jbase = jb0 + wn * 16;

    float bir[2][2], biz[2][2], bin_[2][2], bhn_[2][2], wo_[2][2];
#pragma unroll
    for (int fh = 0; fh < 2; ++fh)
#pragma unroll
        for (int cs = 0; cs < 2; ++cs) {
            int j = jbase + 8 * fh + 2 * tig + cs;
            bir[fh][cs] = bih[j] + bhh[j];
            biz[fh][cs] = bih[H_SZ + j] + bhh[H_SZ + j];
            bin_[fh][cs] = bih[2 * H_SZ + j];
            bhn_[fh][cs] = bhh[2 * H_SZ + j];
            wo_[fh][cs] = Wo[j];
        }

    auto load_chunk = [&](const float* Asrc, int lda, int kb, const float* Bsrc, int s) {
        float* Ad = smem + s * STAGE_FLOATS;
        float* Bd = Ad + A_ROWS * PITCH;
#pragma unroll
        for (int i = 0; i < 8; ++i) {
            int idx = tidg + i * 128;
            int r = idx >> 4, c4 = (idx & 15) * 4;
            cp16(Ad + r * PITCH + c4, Asrc + (size_t)r * lda + kb + c4);
        }
#pragma unroll
        for (int i = 0; i < 12; ++i) {
            int idx = tidg + i * 128;
            int rl = idx >> 4, c4 = (idx & 15) * 4;
            int gg = rl / 48, rem = rl - gg * 48;
            int gate = rem >> 4, unit = rem & 15;
            int grow = gate * H_SZ + jb0 + gg * 16 + unit;
            cp16(Bd + rl * PITCH + c4, Bsrc + (size_t)grow * lda + kb + c4);
        }
        cp_commit();
    };

    // g0 chunk c: 0 = x(t)@Wih, 1..8 = h@Whh K[(c-1)*64,...), 9 = x(t+1)@Wih prefetch
    auto issue0 = [&](int c, int t) {
        int s = c % 3;
        if (c == 0 || c == 9) {
            int tt = (c == 9) ? ((t + 1 < T_SZ) ? t + 1 : t) : t;
            load_chunk(curr + (size_t)tt * (B_SZ * WS) + (size_t)m0 * WS, WS, 0, Wih, s);
        } else {
            load_chunk(g_hbuf[t & 1] + (size_t)m0 * H_SZ, H_SZ, (c - 1) * KC, Whh, s);
        }
    };
    // g1 chunk c: h@Whh K[512 + c*64, ...)
    auto issue1 = [&](int c, int t) {
        load_chunk(g_hbuf[t & 1] + (size_t)m0 * H_SZ, H_SZ, 512 + c * KC, Whh, 3 + (c & 1));
    };

    float acc[2][6][4], acci[2][2][4];

    auto compute = [&](const float* Ad) {
        const float* Bd = Ad + A_ROWS * PITCH;
#pragma unroll
        for (int kk = 0; kk < 8; ++kk) {
            const int kc = kk * 8;
            uint32_t a[2][4];
#pragma unroll
            for (int mf = 0; mf < 2; ++mf) {
                const float* p = Ad + (wrow + 16 * mf + gid) * PITCH + kc + tig;
                a[mf][0] = __float_as_uint(p[0]);
                a[mf][1] = __float_as_uint(p[8 * PITCH]);
                a[mf][2] = __float_as_uint(p[4]);
                a[mf][3] = __float_as_uint(p[8 * PITCH + 4]);
            }
#pragma unroll
            for (int f = 0; f < 6; ++f) {
                const float* q = Bd + (cb + 8 * f + gid) * PITCH + kc + tig;
                uint32_t b0 = __float_as_uint(q[0]);
                uint32_t b1 = __float_as_uint(q[4]);
#pragma unroll
                for (int mf = 0; mf < 2; ++mf) {
                    asm("mma.sync.aligned.m16n8k8.row.col.f32.tf32.tf32.f32 "
                        "{%0,%1,%2,%3}, {%4,%5,%6,%7}, {%8,%9}, {%0,%1,%2,%3};"
                        : "+f"(acc[mf][f][0]), "+f"(acc[mf][f][1]),
                          "+f"(acc[mf][f][2]), "+f"(acc[mf][f][3])
                        : "r"(a[mf][0]), "r"(a[mf][1]), "r"(a[mf][2]), "r"(a[mf][3]),
                          "r"(b0), "r"(b1));
                }
            }
        }
    };

    if (grp == 0) issue0(0, 0);  // x(0) -> stage 0

    for (int t = 0; t < T_SZ; ++t) {
        const float* hprev = g_hbuf[t & 1];
        float* hnext = g_hbuf[(t + 1) & 1];

#pragma unroll
        for (int mf = 0; mf < 2; ++mf)
#pragma unroll
            for (int f = 0; f < 6; ++f)
#pragma unroll
                for (int e = 0; e < 4; ++e) acc[mf][f][e] = 0.f;

        if (grp == 0) {
            issue0(1, t);
#pragma unroll 1
            for (int c = 0; c < 9; ++c) {
                cp_wait<1>();
                BAR_G0();
                if (c <= 7) issue0(c + 2, t);  // safe: all warps finished compute(c-1)
                compute(smem + (c % 3) * STAGE_FLOATS);
                if (c == 0) {  // only the n-gate needs the input part kept separate
#pragma unroll
                    for (int mf = 0; mf < 2; ++mf)
#pragma unroll
                        for (int fh = 0; fh < 2; ++fh)
#pragma unroll
                            for (int e = 0; e < 4; ++e) {
                                acci[mf][fh][e] = acc[mf][4 + fh][e];
                                acc[mf][4 + fh][e] = 0.f;
                            }
                }
            }

            BAR_ALL();  // group 1's partials are in red
            {
                float* a = &acc[0][0][0];
#pragma unroll
                for (int q = 0; q < 12; ++q) {
                    float4 v = *(const float4*)(red + tidg * RED_PITCH + q * 4);
                    a[q * 4 + 0] += v.x; a[q * 4 + 1] += v.y;
                    a[q * 4 + 2] += v.z; a[q * 4 + 3] += v.w;
                }
            }

            // ---- gates + head + state write ----
            float ps[4] = {0.f, 0.f, 0.f, 0.f};
#pragma unroll
            for (int mf = 0; mf < 2; ++mf)
#pragma unroll
                for (int fh = 0; fh < 2; ++fh)
#pragma unroll
                    for (int cs = 0; cs < 2; ++cs) {
                        int j = jbase + 8 * fh + 2 * tig + cs;
#pragma unroll
                        for (int rs = 0; rs < 2; ++rs) {
                            int e = rs * 2 + cs;
                            int b = m0 + wrow + 16 * mf + gid + 8 * rs;
                            float r = sigmoidf_(acc[mf][fh][e] + bir[fh][cs]);
                            float z = sigmoidf_(acc[mf][2 + fh][e] + biz[fh][cs]);
                            float n = tanhf(acci[mf][fh][e] + bin_[fh][cs] +
                                            r * (acc[mf][4 + fh][e] + bhn_[fh][cs]));
                            float hold = hprev[b * H_SZ + j];
                            float hv = (1.f - z) * n + z * hold;
                            hnext[b * H_SZ + j] = rna_tf32(hv);
                            ps[mf * 2 + rs] += hv * wo_[fh][cs];
                        }
                    }
#pragma unroll
            for (int i = 0; i < 4; ++i) {
                ps[i] += __shfl_xor_sync(0xffffffffu, ps[i], 1);
                ps[i] += __shfl_xor_sync(0xffffffffu, ps[i], 2);
            }
            if (tig == 0) {
#pragma unroll
                for (int i = 0; i < 4; ++i) {
                    int b = m0 + wrow + 16 * (i >> 1) + gid + 8 * (i & 1);
                    atomicAdd(out + b * T_SZ + t, ps[i]);
                }
            }

            if (t + 1 < T_SZ) grid_bar(base + 3 + t, tid);
        } else {
            issue1(0, t);
#pragma unroll 1
            for (int c = 0; c < 8; ++c) {
                cp_wait<0>();
                BAR_G1();
                if (c <= 6) issue1(c + 1, t);
                compute(smem + (3 + (c & 1)) * STAGE_FLOATS);
            }
            {   // export partials into red (stage-3 region is fully consumed by now)
                const float* a = &acc[0][0][0];
#pragma unroll
                for (int q = 0; q < 12; ++q) {
                    float4 v = make_float4(a[q * 4 + 0], a[q * 4 + 1],
                                           a[q * 4 + 2], a[q * 4 + 3]);
                    *(float4*)(red + tidg * RED_PITCH + q * 4) = v;
                }
            }
            BAR_ALL();  // partials ready for group 0

            if (t + 1 < T_SZ) grid_bar(base + 3 + t, tid);
        }
    }
    cp_wait<0>();  // drain the final dummy x prefetch
}

// ================= launch =================
extern "C" void kernel_launch(void* const* d_in, const int* in_sizes, int n_in,
                              void* d_out, int out_size) {
    const float* lag  = (const float*)d_in[0];
    const float* curr = (const float*)d_in[1];
    const float* W1   = (const float*)d_in[2];
    const float* b1   = (const float*)d_in[3];
    const float* W2   = (const float*)d_in[4];
    const float* b2   = (const float*)d_in[5];
    const float* W3   = (const float*)d_in[6];
    const float* b3   = (const float*)d_in[7];
    const float* Wih  = (const float*)d_in[8];
    const float* Whh  = (const float*)d_in[9];
    const float* bih  = (const float*)d_in[10];
    const float* bhh  = (const float*)d_in[11];
    const float* Wo   = (const float*)d_in[12];
    const float* bo   = (const float*)d_in[13];
    float* out = (float*)d_out;

    const size_t SMEM = (size_t)(5 * STAGE_FLOATS) * sizeof(float);  // 217600 B
    cudaFuncSetAttribute(crnn_all, cudaFuncAttributeMaxDynamicSharedMemorySize, (int)SMEM);

    crnn_all<<<GRID_CTAS, NTHREADS, SMEM>>>(lag, curr, W1, b1, W2, b2, W3, b3,
                                            Wih, Whh, bih, bhh, Wo, bo, out);
}

// round 12
// speedup vs baseline: 1.0136x; 1.0136x over previous
#include <cuda_runtime.h>
#include <cstdint>

#define B_SZ 256
#define T_SZ 168
#define LAG 168
#define LAT 128
#define WS 64
#define H_SZ 1024

#define KC 64
#define PITCH 68                 // 68 % 32 == 4 -> conflict-free frag reads
#define A_ROWS 64
#define B_ROWS 96
#define STAGE_FLOATS ((A_ROWS + B_ROWS) * PITCH)   // 10880 floats / stage
#define RED_PITCH 52
#define GRID_CTAS 128
#define NTHREADS 256

// ---- device scratch (no allocations allowed) ----
__device__ float g_hbuf[2][B_SZ * H_SZ];   // ping-pong GRU state
__device__ float g_e2[B_SZ * LAT];
__device__ unsigned g_cnt;                 // grid barrier arrivals (monotonic, replay-safe)
__device__ unsigned g_gen;                 // grid barrier generation (monotonic)

__device__ __forceinline__ float leakyf(float x) { return x >= 0.f ? x : 0.01f * x; }
__device__ __forceinline__ float sigmoidf_(float x) { return 1.f / (1.f + expf(-x)); }
__device__ __forceinline__ float rna_tf32(float x) {
    uint32_t o;
    asm("cvt.rna.tf32.f32 %0, %1;" : "=r"(o) : "f"(x));
    return __uint_as_float(o);
}
__device__ __forceinline__ void cp16(void* sdst, const void* gsrc) {
    uint32_t s = (uint32_t)__cvta_generic_to_shared(sdst);
    asm volatile("cp.async.cg.shared.global [%0], [%1], 16;" ::"r"(s), "l"(gsrc));
}
__device__ __forceinline__ void cp_commit() { asm volatile("cp.async.commit_group;"); }
template <int N>
__device__ __forceinline__ void cp_wait() { asm volatile("cp.async.wait_group %0;" ::"n"(N)); }

#define BAR_ALL() asm volatile("bar.sync 0, 256;" ::: "memory")
#define BAR_G0()  asm volatile("bar.sync 1, 128;" ::: "memory")
#define BAR_G1()  asm volatile("bar.sync 2, 128;" ::: "memory")

// Grid barrier: wait until all 128 CTAs reach generation `target` (absolute,
// computed from the g_gen snapshot taken at kernel entry -> replay-safe).
__device__ __forceinline__ void grid_bar(unsigned target, int tid) {
    __threadfence();
    BAR_ALL();
    if (tid == 0) {
        unsigned prev = atomicAdd(&g_cnt, 1u);
        if (prev + 1u == target * (unsigned)GRID_CTAS) {
            __threadfence();
            *(volatile unsigned*)&g_gen = target;
        } else {
            while ((int)(*(volatile unsigned*)&g_gen - target) < 0) {}
        }
        __threadfence();
    }
    BAR_ALL();
}

// ================= the whole model, one persistent kernel =================
// grid = 128 CTAs = 4 m-tiles (64 batch rows) x 32 n-tiles (32 hidden units).
// 8 warps: warps 0-3 = K-group 0 (input GEMM + hidden K[0,512), stages 0-2),
//          warps 4-7 = K-group 1 (hidden K[512,1024), stages 3-4).
// Each group: 2m x 2n warps, warp tile 32 rows x 48 gate cols, tf32 m16n8k8.
__global__ void __launch_bounds__(NTHREADS, 1) crnn_all(
    const float* __restrict__ lag, const float* __restrict__ curr,
    const float* __restrict__ W1, const float* __restrict__ b1,
    const float* __restrict__ W2, const float* __restrict__ b2,
    const float* __restrict__ W3, const float* __restrict__ b3,
    const float* __restrict__ Wih, const float* __restrict__ Whh,
    const float* __restrict__ bih, const float* __restrict__ bhh,
    const float* __restrict__ Wo, const float* __restrict__ bo,
    float* __restrict__ out) {
    extern __shared__ float smem[];
    float* red = smem + 3 * STAGE_FLOATS;  // reuses stage-3 region at exchange time

    const int tid = threadIdx.x;
    const int blk = blockIdx.x;
    const unsigned base = *(volatile unsigned*)&g_gen;  // entry snapshot (stable: no CTA
                                                        // bumps g_gen before all read it)

    // ---------------- phase E: out init + enc1 + enc2 (2 batch rows / CTA) ----------------
    {
        float bov = bo[0];
        for (int i = tid; i < 336; i += NTHREADS) out[blk * 336 + i] = bov;
        int hid = tid >> 7, ht = tid & 127;
        int row = blk * 2 + hid;
        float* lagbuf = smem + hid * LAG;
        float* e1buf = smem + 2 * LAG + hid * 64;
        for (int i = ht; i < LAG; i += 128) lagbuf[i] = lag[row * LAG + i];
        __syncthreads();
        if (ht < 64) {
            float acc = b1[ht];
            const float* w = W1 + ht * LAG;
#pragma unroll 4
            for (int k = 0; k < LAG; ++k) acc += lagbuf[k] * w[k];
            e1buf[ht] = leakyf(acc);
        }
        __syncthreads();
        {
            float acc = b2[ht];
            const float* w = W2 + ht * 64;
#pragma unroll 8
            for (int k = 0; k < 64; ++k) acc += e1buf[k] * w[k];
            g_e2[row * LAT + ht] = leakyf(acc);
        }
    }
    grid_bar(base + 1, tid);

    // ---------------- phase E3: h0 = leaky-free (e2 @ W3.T + b3), 2 rows / CTA ----------------
    {
        float* e2buf = smem;
        e2buf[tid] = g_e2[blk * 256 + tid];
        __syncthreads();
#pragma unroll
        for (int rr = 0; rr < 2; ++rr)
#pragma unroll
            for (int q = 0; q < 4; ++q) {
                int col = tid + q * 256;
                float acc = b3[col];
                const float* w = W3 + (size_t)col * LAT;
                const float* e = e2buf + rr * LAT;
#pragma unroll 8
                for (int k = 0; k < LAT; ++k) acc += e[k] * w[k];
                g_hbuf[0][(size_t)(blk * 2 + rr) * H_SZ + col] = rna_tf32(acc);
            }
    }
    grid_bar(base + 2, tid);

    // ---------------- persistent GRU ----------------
    const int warp = tid >> 5, lane = tid & 31;
    const int gid = lane >> 2, tig = lane & 3;
    const int grp = warp >> 2;
    const int wi = warp & 3;
    const int wm = wi & 1, wn = wi >> 1;
    const int wrow = wm * 32;
    const int cb = wn * 48;
    const int tidg = tid & 127;
    const int nt = blk & 31, mt = blk >> 5;
    const int m0 = mt * 64;
    const int jb0 = nt * 32;
    const int jbase = jb0 + wn * 16;

    float bir[2][2], biz[2][2], bin_[2][2], bhn_[2][2], wo_[2][2];
#pragma unroll
    for (int fh = 0; fh < 2; ++fh)
#pragma unroll
        for (int cs = 0; cs < 2; ++cs) {
            int j = jbase + 8 * fh + 2 * tig + cs;
            bir[fh][cs] = bih[j] + bhh[j];
            biz[fh][cs] = bih[H_SZ + j] + bhh[H_SZ + j];
            bin_[fh][cs] = bih[2 * H_SZ + j];
            bhn_[fh][cs] = bhh[2 * H_SZ + j];
            wo_[fh][cs] = Wo[j];
        }

    auto load_chunk = [&](const float* Asrc, int lda, int kb, const float* Bsrc, int s) {
        float* Ad = smem + s * STAGE_FLOATS;
        float* Bd = Ad + A_ROWS * PITCH;
#pragma unroll
        for (int i = 0; i < 8; ++i) {
            int idx = tidg + i * 128;
            int r = idx >> 4, c4 = (idx & 15) * 4;
            cp16(Ad + r * PITCH + c4, Asrc + (size_t)r * lda + kb + c4);
        }
#pragma unroll
        for (int i = 0; i < 12; ++i) {
            int idx = tidg + i * 128;
            int rl = idx >> 4, c4 = (idx & 15) * 4;
            int gg = rl / 48, rem = rl - gg * 48;
            int gate = rem >> 4, unit = rem & 15;
            int grow = gate * H_SZ + jb0 + gg * 16 + unit;
            cp16(Bd + rl * PITCH + c4, Bsrc + (size_t)grow * lda + kb + c4);
        }
        cp_commit();
    };

    // g0 chunk c: 0 = x(t)@Wih, 1..8 = h@Whh K[(c-1)*64,...), 9 = x(t+1)@Wih prefetch
    auto issue0 = [&](int c, int t) {
        int s = c % 3;
        if (c == 0 || c == 9) {
            int tt = (c == 9) ? ((t + 1 < T_SZ) ? t + 1 : t) : t;
            load_chunk(curr + (size_t)tt * (B_SZ * WS) + (size_t)m0 * WS, WS, 0, Wih, s);
        } else {
            load_chunk(g_hbuf[t & 1] + (size_t)m0 * H_SZ, H_SZ, (c - 1) * KC, Whh, s);
        }
    };
    // g1 chunk c: h@Whh K[512 + c*64, ...)
    auto issue1 = [&](int c, int t) {
        load_chunk(g_hbuf[t & 1] + (size_t)m0 * H_SZ, H_SZ, 512 + c * KC, Whh, 3 + (c & 1));
    };

    float acc[2][6][4], acci[2][2][4];

    auto compute = [&](const float* Ad) {
        const float* Bd = Ad + A_ROWS * PITCH;
#pragma unroll
        for (int kk = 0; kk < 8; ++kk) {
            const int kc = kk * 8;
            uint32_t a[2][4];
#pragma unroll
            for (int mf = 0; mf < 2; ++mf) {
                const float* p = Ad + (wrow + 16 * mf + gid) * PITCH + kc + tig;
                a[mf][0] = __float_as_uint(p[0]);
                a[mf][1] = __float_as_uint(p[8 * PITCH]);
                a[mf][2] = __float_as_uint(p[4]);
                a[mf][3] = __float_as_uint(p[8 * PITCH + 4]);
            }
#pragma unroll
            for (int f = 0; f < 6; ++f) {
                const float* q = Bd + (cb + 8 * f + gid) * PITCH + kc + tig;
                uint32_t b0 = __float_as_uint(q[0]);
                uint32_t b1 = __float_as_uint(q[4]);
#pragma unroll
                for (int mf = 0; mf < 2; ++mf) {
                    asm("mma.sync.aligned.m16n8k8.row.col.f32.tf32.tf32.f32 "
                        "{%0,%1,%2,%3}, {%4,%5,%6,%7}, {%8,%9}, {%0,%1,%2,%3};"
                        : "+f"(acc[mf][f][0]), "+f"(acc[mf][f][1]),
                          "+f"(acc[mf][f][2]), "+f"(acc[mf][f][3])
                        : "r"(a[mf][0]), "r"(a[mf][1]), "r"(a[mf][2]), "r"(a[mf][3]),
                          "r"(b0), "r"(b1));
                }
            }
        }
    };

    if (grp == 0) issue0(0, 0);  // x(0) -> stage 0

    for (int t = 0; t < T_SZ; ++t) {
        const float* hprev = g_hbuf[t & 1];
        float* hnext = g_hbuf[(t + 1) & 1];

#pragma unroll
        for (int mf = 0; mf < 2; ++mf)
#pragma unroll
            for (int f = 0; f < 6; ++f)
#pragma unroll
                for (int e = 0; e < 4; ++e) acc[mf][f][e] = 0.f;

        if (grp == 0) {
            issue0(1, t);
#pragma unroll 1
            for (int c = 0; c < 9; ++c) {
                cp_wait<1>();
                BAR_G0();
                if (c <= 7) issue0(c + 2, t);  // safe: all warps finished compute(c-1)
                compute(smem + (c % 3) * STAGE_FLOATS);
                if (c == 0) {  // only the n-gate needs the input part kept separate
#pragma unroll
                    for (int mf = 0; mf < 2; ++mf)
#pragma unroll
                        for (int fh = 0; fh < 2; ++fh)
#pragma unroll
                            for (int e = 0; e < 4; ++e) {
                                acci[mf][fh][e] = acc[mf][4 + fh][e];
                                acc[mf][4 + fh][e] = 0.f;
                            }
                }
            }

            BAR_ALL();  // group 1's partials are in red
            {
                float* a = &acc[0][0][0];
#pragma unroll
                for (int q = 0; q < 12; ++q) {
                    float4 v = *(const float4*)(red + tidg * RED_PITCH + q * 4);
                    a[q * 4 + 0] += v.x; a[q * 4 + 1] += v.y;
                    a[q * 4 + 2] += v.z; a[q * 4 + 3] += v.w;
                }
            }

            // ---- gates + head + state write ----
            float ps[4] = {0.f, 0.f, 0.f, 0.f};
#pragma unroll
            for (int mf = 0; mf < 2; ++mf)
#pragma unroll
                for (int fh = 0; fh < 2; ++fh)
#pragma unroll
                    for (int cs = 0; cs < 2; ++cs) {
                        int j = jbase + 8 * fh + 2 * tig + cs;
#pragma unroll
                        for (int rs = 0; rs < 2; ++rs) {
                            int e = rs * 2 + cs;
                            int b = m0 + wrow + 16 * mf + gid + 8 * rs;
                            float r = sigmoidf_(acc[mf][fh][e] + bir[fh][cs]);
                            float z = sigmoidf_(acc[mf][2 + fh][e] + biz[fh][cs]);
                            float n = tanhf(acci[mf][fh][e] + bin_[fh][cs] +
                                            r * (acc[mf][4 + fh][e] + bhn_[fh][cs]));
                            float hold = hprev[b * H_SZ + j];
                            float hv = (1.f - z) * n + z * hold;
                            hnext[b * H_SZ + j] = rna_tf32(hv);
                            ps[mf * 2 + rs] += hv * wo_[fh][cs];
                        }
                    }
#pragma unroll
            for (int i = 0; i < 4; ++i) {
                ps[i] += __shfl_xor_sync(0xffffffffu, ps[i], 1);
                ps[i] += __shfl_xor_sync(0xffffffffu, ps[i], 2);
            }
            if (tig == 0) {
#pragma unroll
                for (int i = 0; i < 4; ++i) {
                    int b = m0 + wrow + 16 * (i >> 1) + gid + 8 * (i & 1);
                    atomicAdd(out + b * T_SZ + t, ps[i]);
                }
            }

            if (t + 1 < T_SZ) grid_bar(base + 3 + t, tid);
        } else {
            issue1(0, t);
#pragma unroll 1
            for (int c = 0; c < 8; ++c) {
                cp_wait<0>();
                BAR_G1();
                if (c <= 6) issue1(c + 1, t);
                compute(smem + (3 + (c & 1)) * STAGE_FLOATS);
            }
            {   // export partials into red (stage-3 region is fully consumed by now)
                const float* a = &acc[0][0][0];
#pragma unroll
                for (int q = 0; q < 12; ++q) {
                    float4 v = make_float4(a[q * 4 + 0], a[q * 4 + 1],
                                           a[q * 4 + 2], a[q * 4 + 3]);
                    *(float4*)(red + tidg * RED_PITCH + q * 4) = v;
                }
            }
            BAR_ALL();  // partials ready for group 0

            if (t + 1 < T_SZ) grid_bar(base + 3 + t, tid);
        }
    }
    cp_wait<0>();  // drain the final dummy x prefetch
}

// ================= launch =================
extern "C" void kernel_launch(void* const* d_in, const int* in_sizes, int n_in,
                              void* d_out, int out_size) {
    const float* lag  = (const float*)d_in[0];
    const float* curr = (const float*)d_in[1];
    const float* W1   = (const float*)d_in[2];
    const float* b1   = (const float*)d_in[3];
    const float* W2   = (const float*)d_in[4];
    const float* b2   = (const float*)d_in[5];
    const float* W3   = (const float*)d_in[6];
    const float* b3   = (const float*)d_in[7];
    const float* Wih  = (const float*)d_in[8];
    const float* Whh  = (const float*)d_in[9];
    const float* bih  = (const float*)d_in[10];
    const float* bhh  = (const float*)d_in[11];
    const float* Wo   = (const float*)d_in[12];
    const float* bo   = (const float*)d_in[13];
    float* out = (float*)d_out;

    const size_t SMEM = (size_t)(5 * STAGE_FLOATS) * sizeof(float);  // 217600 B
    cudaFuncSetAttribute(crnn_all, cudaFuncAttributeMaxDynamicSharedMemorySize, (int)SMEM);

    crnn_all<<<GRID_CTAS, NTHREADS, SMEM>>>(lag, curr, W1, b1, W2, b2, W3, b3,
                                            Wih, Whh, bih, bhh, Wo, bo, out);
}